// round 15
// baseline (speedup 1.0000x reference)
#include <cuda_runtime.h>
#include <cuda_fp16.h>
#include <math.h>
#include <stdint.h>

#define B_SZ  8
#define S_LEN 1024
#define NH    16
#define NKV   4
#define HD    128
#define DIM   2048
#define MTOT  (B_SZ * S_LEN)   // 8192
#define KVD   (NKV * HD)       // 512
#define QKVN  (DIM + 2 * KVD)  // 3072
#define QKEND (DIM + KVD)      // 2560: cols < this get RoPE

#define GEMM_GRID 444           // 148 SMs * 3 CTAs/SM

// ---------------- static scratch (allocation-free) ----------------
__device__ __half g_qkvh[(size_t)MTOT * QKVN];   // fused Q|K|V fp16 (rope applied, Q pre-scaled)
__device__ __half g_xh[(size_t)MTOT * DIM];      // x fp16
__device__ __half g_oh[(size_t)MTOT * DIM];      // attn out fp16
__device__ __half g_wf[(size_t)QKVN * DIM];      // fused wq|wk|wv fp16
__device__ __half g_wo2[(size_t)DIM * DIM];      // wo fp16
__device__ unsigned int g_tile_ctr[2];           // persistent-GEMM tile counters

// ---------------- helpers ----------------
__device__ __forceinline__ uint32_t smem_u32(const void* p) {
    uint32_t a;
    asm("{ .reg .u64 t; cvta.to.shared.u64 t, %1; cvt.u32.u64 %0, t; }" : "=r"(a) : "l"(p));
    return a;
}

__device__ __forceinline__ void ldsm_x4(uint32_t* r, uint32_t addr) {
    asm volatile("ldmatrix.sync.aligned.m8n8.x4.shared.b16 {%0,%1,%2,%3}, [%4];"
        : "=r"(r[0]), "=r"(r[1]), "=r"(r[2]), "=r"(r[3]) : "r"(addr));
}
__device__ __forceinline__ void ldsm_x4_trans(uint32_t* r, uint32_t addr) {
    asm volatile("ldmatrix.sync.aligned.m8n8.x4.trans.shared.b16 {%0,%1,%2,%3}, [%4];"
        : "=r"(r[0]), "=r"(r[1]), "=r"(r[2]), "=r"(r[3]) : "r"(addr));
}

__device__ __forceinline__ void mma16816(float* d, const uint32_t* a, const uint32_t* b) {
    asm volatile("mma.sync.aligned.m16n8k16.row.col.f32.f16.f16.f32 "
        "{%0,%1,%2,%3}, {%4,%5,%6,%7}, {%8,%9}, {%0,%1,%2,%3};"
        : "+f"(d[0]), "+f"(d[1]), "+f"(d[2]), "+f"(d[3])
        : "r"(a[0]), "r"(a[1]), "r"(a[2]), "r"(a[3]), "r"(b[0]), "r"(b[1]));
}

__device__ __forceinline__ uint32_t packh2(float lo, float hi) {
    __half2 h = __floats2half2_rn(lo, hi);
    return *(uint32_t*)&h;
}

// =====================================================================
// fused convert: all fp32 weights/activations -> fp16, 2 float4/thread
// =====================================================================
#define CVT_TOTAL4 6815744
#define CVT_THREADS (CVT_TOTAL4 / 2)

__global__ void convert_all(const float* __restrict__ wq, const float* __restrict__ wk,
                            const float* __restrict__ wv, const float* __restrict__ wo,
                            const float* __restrict__ x,
                            __half* __restrict__ wf, __half* __restrict__ wo2,
                            __half* __restrict__ xh) {
    int t = blockIdx.x * 256 + threadIdx.x;
    if (t >= CVT_THREADS) return;
#pragma unroll
    for (int u = 0; u < 2; u++) {
        int i = t * 2 + u;
        const float* src;
        __half* dst;
        int off;
        if (i < 1048576)       { src = wq; dst = wf;                             off = i; }
        else if (i < 1310720)  { src = wk; dst = wf + (size_t)DIM * DIM;         off = i - 1048576; }
        else if (i < 1572864)  { src = wv; dst = wf + (size_t)(DIM + KVD) * DIM; off = i - 1310720; }
        else if (i < 2621440)  { src = wo; dst = wo2;                            off = i - 1572864; }
        else                   { src = x;  dst = xh;                             off = i - 2621440; }
        float4 v = ((const float4*)src)[off];
        __half2* op = (__half2*)dst;
        op[off * 2 + 0] = __floats2half2_rn(v.x, v.y);
        op[off * 2 + 1] = __floats2half2_rn(v.z, v.w);
    }
}

// =====================================================================
// Persistent GEMM via mma.sync fp16: C[M,N] = A @ B^T, fp32 accum.
// CTA tile 128x128, BK=64, 128 threads (4 warps, warp tile 64x64),
// double-buffered cp.async, 3 CTAs/SM, atomic tile scheduler.
// =====================================================================
#define TILE_B   18432          // 128 rows * 144 B
#define STAGE_B  (2 * TILE_B)   // 36864
#define GEMM_SMEM_BYTES (2 * STAGE_B + 16)  // +16 for tile-id broadcast

__device__ __forceinline__ void gemm_load_chunk(
    const __half* __restrict__ A, const __half* __restrict__ B,
    int bm, int bn, int K, int kc, uint32_t stbase, int tid) {
#pragma unroll
    for (int t = 0; t < 16; t++) {
        const int tile = t >> 3;                  // 0:A 1:B (compile-time)
        const int rem  = tid + (t & 7) * 128;     // 0..1023
        const int row  = rem >> 3;
        const int seg  = rem & 7;
        const __half* base = (tile == 0) ? A : B;
        const int grow = ((tile == 0) ? bm : bn) + row;
        const void* g = base + (size_t)grow * K + kc * 64 + seg * 8;
        uint32_t dst = stbase + (uint32_t)tile * TILE_B + (uint32_t)(row * 144 + seg * 16);
        asm volatile("cp.async.cg.shared.global [%0], [%1], 16;" :: "r"(dst), "l"(g) : "memory");
    }
    asm volatile("cp.async.commit_group;" ::: "memory");
}

template <bool ROPE_F16>
__global__ __launch_bounds__(128, 3)
void gemm_f16(const __half* __restrict__ A, const __half* __restrict__ B,
              void* __restrict__ Cout, int N, int K,
              const float* __restrict__ cosT, const float* __restrict__ sinT,
              int nbx, int ntiles, unsigned int* __restrict__ ctr) {
    extern __shared__ char smem_raw[];
    const uint32_t sbase = smem_u32(smem_raw);
    volatile unsigned int* s_tile = (volatile unsigned int*)(smem_raw + 2 * STAGE_B);

    const int tid  = threadIdx.x;
    const int wid  = tid >> 5;
    const int lane = tid & 31;
    const int warp_m = wid & 1;        // 2 warps along M (64 rows each)
    const int warp_n = wid >> 1;       // 2 warps along N (64 cols each)

    const uint32_t a_row = (uint32_t)(warp_m * 64 + (lane & 15));
    const uint32_t a_off = a_row * 144u + (uint32_t)((lane >> 4) * 16);
    const uint32_t b_row = (uint32_t)(warp_n * 64 + (lane & 7) + ((lane >> 4) & 1) * 8);
    const uint32_t b_off = b_row * 144u + (uint32_t)(((lane >> 3) & 1) * 16);

    const int NCHUNK = K >> 6;   // BK = 64
    const float qscale = 0.08838834764831845f;  // 1/sqrt(128)
    const int crow = lane >> 2;
    const int ccol = (lane & 3) * 2;

    for (;;) {
        if (tid == 0) *s_tile = atomicAdd(ctr, 1u);
        __syncthreads();
        const unsigned int tile = *s_tile;
        if (tile >= (unsigned int)ntiles) return;
        const int bm = (int)(tile / (unsigned)nbx) * 128;
        const int bn = (int)(tile % (unsigned)nbx) * 128;

        float acc[4][8][4];
#pragma unroll
        for (int i = 0; i < 4; i++)
#pragma unroll
            for (int j = 0; j < 8; j++)
#pragma unroll
                for (int v = 0; v < 4; v++) acc[i][j][v] = 0.0f;

        gemm_load_chunk(A, B, bm, bn, K, 0, sbase, tid);

        for (int c = 0; c < NCHUNK; c++) {
            asm volatile("cp.async.wait_group 0;" ::: "memory");
            __syncthreads();
            if (c + 1 < NCHUNK)
                gemm_load_chunk(A, B, bm, bn, K, c + 1,
                                sbase + (uint32_t)((c + 1) & 1) * STAGE_B, tid);

            const uint32_t stage = (uint32_t)(c & 1) * STAGE_B;
#pragma unroll
            for (int ks = 0; ks < 4; ks++) {
                const uint32_t aa = sbase + stage + a_off + (uint32_t)ks * 32u;
                const uint32_t bb = sbase + stage + TILE_B + b_off + (uint32_t)ks * 32u;
                uint32_t af[4][4];
#pragma unroll
                for (int mt = 0; mt < 4; mt++)
                    ldsm_x4(af[mt], aa + (uint32_t)mt * (16u * 144u));
#pragma unroll
                for (int nbh = 0; nbh < 2; nbh++) {
                    uint32_t bf0[4], bf1[4];
                    ldsm_x4(bf0, bb + (uint32_t)(nbh * 2 + 0) * (16u * 144u));
                    ldsm_x4(bf1, bb + (uint32_t)(nbh * 2 + 1) * (16u * 144u));
#pragma unroll
                    for (int mt = 0; mt < 4; mt++) {
                        mma16816(acc[mt][nbh * 4 + 0], af[mt], &bf0[0]);
                        mma16816(acc[mt][nbh * 4 + 1], af[mt], &bf0[2]);
                        mma16816(acc[mt][nbh * 4 + 2], af[mt], &bf1[0]);
                        mma16816(acc[mt][nbh * 4 + 3], af[mt], &bf1[2]);
                    }
                }
            }
        }

#pragma unroll
        for (int mt = 0; mt < 4; mt++) {
#pragma unroll
            for (int nt = 0; nt < 8; nt++) {
                const int row = bm + warp_m * 64 + mt * 16 + crow;
                const int col = bn + warp_n * 64 + nt * 8 + ccol;
                if (ROPE_F16) {
                    float2 v0 = make_float2(acc[mt][nt][0], acc[mt][nt][1]);
                    float2 v1 = make_float2(acc[mt][nt][2], acc[mt][nt][3]);
                    if (col < QKEND) {
                        const int j  = (col & (HD - 1)) >> 1;
                        const int s0 = row & (S_LEN - 1);
                        const int s1 = (row + 8) & (S_LEN - 1);
                        float c0 = cosT[s0 * 64 + j], n0 = sinT[s0 * 64 + j];
                        float c1 = cosT[s1 * 64 + j], n1 = sinT[s1 * 64 + j];
                        v0 = make_float2(v0.x * c0 - v0.y * n0, v0.x * n0 + v0.y * c0);
                        v1 = make_float2(v1.x * c1 - v1.y * n1, v1.x * n1 + v1.y * c1);
                    }
                    if (col < DIM) {   // Q region: fold attention scale
                        v0.x *= qscale; v0.y *= qscale;
                        v1.x *= qscale; v1.y *= qscale;
                    }
                    __half* Ch = (__half*)Cout;
                    *(uint32_t*)&Ch[(size_t)row * N + col]       = packh2(v0.x, v0.y);
                    *(uint32_t*)&Ch[(size_t)(row + 8) * N + col] = packh2(v1.x, v1.y);
                } else {
                    float* Cf = (float*)Cout;
                    *(float2*)&Cf[(size_t)row * N + col]       = make_float2(acc[mt][nt][0], acc[mt][nt][1]);
                    *(float2*)&Cf[(size_t)(row + 8) * N + col] = make_float2(acc[mt][nt][2], acc[mt][nt][3]);
                }
            }
        }
    }
}

// =====================================================================
// Tensor-core flash attention (causal, GQA).
// BM=128, BN=64, D=128, 256 threads (8 warps, each owns 16 q-rows).
// Q pre-scaled by 1/sqrt(128) in the QKV epilogue.
// =====================================================================
#define FLA_KV_B    (64 * 136 * 2)                 // 17408 B
#define FLA_Q_B     (128 * 136 * 2)                // 34816 B
#define FLASH_SMEM_BYTES (FLA_Q_B + 4 * FLA_KV_B)  // 104448

__device__ __forceinline__ void fla_load_kv(const __half* src, uint32_t dst, int tid) {
#pragma unroll
    for (int i = 0; i < 4; i++) {
        int s = tid + i * 256;
        int row = s >> 4, seg = s & 15;
        const void* g = src + (size_t)row * QKVN + seg * 8;
        asm volatile("cp.async.cg.shared.global [%0], [%1], 16;"
            :: "r"(dst + (uint32_t)(row * 272 + seg * 16)), "l"(g) : "memory");
    }
}

__global__ __launch_bounds__(256)
void flash_mma(const __half* __restrict__ QKVh, __half* __restrict__ Oh) {
    const int qt = blockIdx.x;          // 0..7 (128-row q tiles)
    const int h  = blockIdx.y;
    const int b  = blockIdx.z;
    const int g  = h >> 2;

    extern __shared__ char smraw[];
    const uint32_t sQ = smem_u32(smraw);
    const uint32_t sK = sQ + FLA_Q_B;
    const uint32_t sV = sK + 2 * FLA_KV_B;

    const int tid  = threadIdx.x;
    const int wid  = tid >> 5;
    const int lane = tid & 31;

    {
        const __half* qsrc = QKVh + (size_t)(b * S_LEN + qt * 128) * QKVN + h * HD;
#pragma unroll
        for (int i = 0; i < 8; i++) {
            int s = tid + i * 256;
            int row = s >> 4, seg = s & 15;
            const void* gp = qsrc + (size_t)row * QKVN + seg * 8;
            asm volatile("cp.async.cg.shared.global [%0], [%1], 16;"
                :: "r"(sQ + (uint32_t)(row * 272 + seg * 16)), "l"(gp) : "memory");
        }
        const __half* ksrc = QKVh + (size_t)(b * S_LEN) * QKVN + DIM + g * HD;
        fla_load_kv(ksrc, sK, tid);
        fla_load_kv(ksrc + KVD, sV, tid);
        asm volatile("cp.async.commit_group;" ::: "memory");
    }

    const uint32_t a_base = sQ + (uint32_t)((wid * 16 + (lane & 15)) * 272 + (lane >> 4) * 16);
    const uint32_t kb_off = (uint32_t)(((lane & 7) + ((lane >> 4) & 1) * 8) * 272 + ((lane >> 3) & 1) * 16);
    const uint32_t vb_off = (uint32_t)(((lane & 7) + ((lane >> 3) & 1) * 8) * 272 + ((lane >> 4) & 1) * 16);

    float o[16][4];
#pragma unroll
    for (int j = 0; j < 16; j++)
#pragma unroll
        for (int v = 0; v < 4; v++) o[j][v] = 0.0f;
    float m0 = -INFINITY, m1 = -INFINITY, l0 = 0.0f, l1 = 0.0f;

    asm volatile("cp.async.wait_group 0;" ::: "memory");
    __syncthreads();

    uint32_t qa[8][4];
#pragma unroll
    for (int ks = 0; ks < 8; ks++) ldsm_x4(qa[ks], a_base + (uint32_t)ks * 32u);

    const int rb0 = wid * 16 + (lane >> 2);
    const int rb1 = rb0 + 8;
    const int cb  = (lane & 3) * 2;
    const int qrow0 = qt * 128 + rb0;
    const int qrow1 = qrow0 + 8;
    const int warp_row_max = qt * 128 + wid * 16 + 15;

    const int njt = 2 * qt + 2;
    for (int jt = 0; jt < njt; jt++) {
        const uint32_t buf = (uint32_t)(jt & 1) * FLA_KV_B;
        if (jt > 0) {
            asm volatile("cp.async.wait_group 0;" ::: "memory");
            __syncthreads();
        }
        if (jt + 1 < njt) {
            const __half* ksrc = QKVh + (size_t)(b * S_LEN + (jt + 1) * 64) * QKVN + DIM + g * HD;
            const uint32_t nbuf = (uint32_t)((jt + 1) & 1) * FLA_KV_B;
            fla_load_kv(ksrc, sK + nbuf, tid);
            fla_load_kv(ksrc + KVD, sV + nbuf, tid);
            asm volatile("cp.async.commit_group;" ::: "memory");
        }

        if (jt * 64 > warp_row_max) continue;

        // ---- S = Q K^T (Q pre-scaled) ----
        float s[8][4];
#pragma unroll
        for (int j = 0; j < 8; j++)
#pragma unroll
            for (int v = 0; v < 4; v++) s[j][v] = 0.0f;

#pragma unroll
        for (int ks = 0; ks < 8; ks++) {
            const uint32_t bb = sK + buf + kb_off + (uint32_t)ks * 32u;
#pragma unroll
            for (int nb = 0; nb < 4; nb++) {
                uint32_t bf[4];
                ldsm_x4(bf, bb + (uint32_t)nb * (16u * 272u));
                mma16816(s[nb * 2 + 0], qa[ks], &bf[0]);
                mma16816(s[nb * 2 + 1], qa[ks], &bf[2]);
            }
        }

        if (jt >= 2 * qt) {
#pragma unroll
            for (int j = 0; j < 8; j++) {
                const int c0 = jt * 64 + j * 8 + cb;
                if (c0 > qrow0)     s[j][0] = -1e30f;
                if (c0 + 1 > qrow0) s[j][1] = -1e30f;
                if (c0 > qrow1)     s[j][2] = -1e30f;
                if (c0 + 1 > qrow1) s[j][3] = -1e30f;
            }
        }

        // ---- online softmax ----
        float mx0 = -INFINITY, mx1 = -INFINITY;
#pragma unroll
        for (int j = 0; j < 8; j++) {
            mx0 = fmaxf(mx0, fmaxf(s[j][0], s[j][1]));
            mx1 = fmaxf(mx1, fmaxf(s[j][2], s[j][3]));
        }
        mx0 = fmaxf(mx0, __shfl_xor_sync(0xffffffffu, mx0, 1));
        mx0 = fmaxf(mx0, __shfl_xor_sync(0xffffffffu, mx0, 2));
        mx1 = fmaxf(mx1, __shfl_xor_sync(0xffffffffu, mx1, 1));
        mx1 = fmaxf(mx1, __shfl_xor_sync(0xffffffffu, mx1, 2));
        const float mn0 = fmaxf(m0, mx0);
        const float mn1 = fmaxf(m1, mx1);
        const float al0 = __expf(m0 - mn0);
        const float al1 = __expf(m1 - mn1);
        m0 = mn0; m1 = mn1;

        float sum0 = 0.0f, sum1 = 0.0f;
#pragma unroll
        for (int j = 0; j < 8; j++) {
            s[j][0] = __expf(s[j][0] - mn0);
            s[j][1] = __expf(s[j][1] - mn0);
            s[j][2] = __expf(s[j][2] - mn1);
            s[j][3] = __expf(s[j][3] - mn1);
            sum0 += s[j][0] + s[j][1];
            sum1 += s[j][2] + s[j][3];
        }
        sum0 += __shfl_xor_sync(0xffffffffu, sum0, 1);
        sum0 += __shfl_xor_sync(0xffffffffu, sum0, 2);
        sum1 += __shfl_xor_sync(0xffffffffu, sum1, 1);
        sum1 += __shfl_xor_sync(0xffffffffu, sum1, 2);
        l0 = l0 * al0 + sum0;
        l1 = l1 * al1 + sum1;

#pragma unroll
        for (int j = 0; j < 16; j++) {
            o[j][0] *= al0; o[j][1] *= al0; o[j][2] *= al1; o[j][3] *= al1;
        }

        // ---- O += P V ----
#pragma unroll
        for (int ksp = 0; ksp < 4; ksp++) {
            uint32_t pa[4];
            pa[0] = packh2(s[2 * ksp][0],     s[2 * ksp][1]);
            pa[1] = packh2(s[2 * ksp][2],     s[2 * ksp][3]);
            pa[2] = packh2(s[2 * ksp + 1][0], s[2 * ksp + 1][1]);
            pa[3] = packh2(s[2 * ksp + 1][2], s[2 * ksp + 1][3]);
            const uint32_t vb = sV + buf + vb_off + (uint32_t)ksp * (16u * 272u);
#pragma unroll
            for (int nb = 0; nb < 8; nb++) {
                uint32_t bf[4];
                ldsm_x4_trans(bf, vb + (uint32_t)nb * 32u);
                mma16816(o[nb * 2 + 0], pa, &bf[0]);
                mma16816(o[nb * 2 + 1], pa, &bf[2]);
            }
        }
    }

    const float inv0 = 1.0f / l0;
    const float inv1 = 1.0f / l1;
    const size_t row0 = (size_t)(b * S_LEN + qt * 128 + rb0);
    const size_t row1 = row0 + 8;
#pragma unroll
    for (int j = 0; j < 16; j++) {
        const int col = h * HD + j * 8 + cb;
        uint32_t p0 = packh2(o[j][0] * inv0, o[j][1] * inv0);
        uint32_t p1 = packh2(o[j][2] * inv1, o[j][3] * inv1);
        *(uint32_t*)&Oh[row0 * DIM + col] = p0;
        *(uint32_t*)&Oh[row1 * DIM + col] = p1;
    }
}

// =====================================================================
// launch
// =====================================================================
extern "C" void kernel_launch(void* const* d_in, const int* in_sizes, int n_in,
                              void* d_out, int out_size) {
    (void)in_sizes; (void)n_in; (void)out_size;
    const float* x    = (const float*)d_in[0];
    const float* cosT = (const float*)d_in[1];
    const float* sinT = (const float*)d_in[2];
    const float* wq   = (const float*)d_in[3];
    const float* wk   = (const float*)d_in[4];
    const float* wv   = (const float*)d_in[5];
    const float* wo   = (const float*)d_in[6];
    float* out = (float*)d_out;

    __half *pqkvh, *xh, *oh, *wf, *wo2;
    unsigned int* ctrs;
    cudaGetSymbolAddress((void**)&pqkvh, g_qkvh);
    cudaGetSymbolAddress((void**)&xh, g_xh);
    cudaGetSymbolAddress((void**)&oh, g_oh);
    cudaGetSymbolAddress((void**)&wf, g_wf);
    cudaGetSymbolAddress((void**)&wo2, g_wo2);
    cudaGetSymbolAddress((void**)&ctrs, g_tile_ctr);

    cudaFuncSetAttribute(flash_mma, cudaFuncAttributeMaxDynamicSharedMemorySize, FLASH_SMEM_BYTES);
    cudaFuncSetAttribute(gemm_f16<true>,  cudaFuncAttributeMaxDynamicSharedMemorySize, GEMM_SMEM_BYTES);
    cudaFuncSetAttribute(gemm_f16<false>, cudaFuncAttributeMaxDynamicSharedMemorySize, GEMM_SMEM_BYTES);

    // reset persistent-GEMM tile counters (graph-capturable memset node)
    cudaMemsetAsync(ctrs, 0, 2 * sizeof(unsigned int));

    // one fused convert launch (2 float4 per thread)
    convert_all<<<(CVT_THREADS + 255) / 256, 256>>>(wq, wk, wv, wo, x, wf, wo2, xh);

    // fused QKV projection with RoPE + Q-scale epilogue, fp16 out (persistent)
    gemm_f16<true><<<GEMM_GRID, 128, GEMM_SMEM_BYTES>>>(
        xh, wf, pqkvh, QKVN, DIM, cosT, sinT,
        QKVN / 128, (QKVN / 128) * (MTOT / 128), ctrs + 0);

    // tensor-core flash attention (writes fp16 O directly)
    flash_mma<<<dim3(S_LEN / 128, NH, B_SZ), 256, FLASH_SMEM_BYTES>>>(pqkvh, oh);

    // output projection (fp32 out, persistent)
    gemm_f16<false><<<GEMM_GRID, 128, GEMM_SMEM_BYTES>>>(
        oh, wo2, out, DIM, DIM, nullptr, nullptr,
        DIM / 128, (DIM / 128) * (MTOT / 128), ctrs + 1);
}

// round 16
// speedup vs baseline: 1.0175x; 1.0175x over previous
#include <cuda_runtime.h>
#include <cuda_fp16.h>
#include <math.h>
#include <stdint.h>

#define B_SZ  8
#define S_LEN 1024
#define NH    16
#define NKV   4
#define HD    128
#define DIM   2048
#define MTOT  (B_SZ * S_LEN)   // 8192
#define KVD   (NKV * HD)       // 512
#define QKVN  (DIM + 2 * KVD)  // 3072
#define QKEND (DIM + KVD)      // 2560: cols < this get RoPE

// ---------------- static scratch (allocation-free) ----------------
__device__ __half g_qkvh[(size_t)MTOT * QKVN];   // fused Q|K|V fp16 (rope applied, Q pre-scaled)
__device__ __half g_xh[(size_t)MTOT * DIM];      // x fp16
__device__ __half g_oh[(size_t)MTOT * DIM];      // attn out fp16
__device__ __half g_wf[(size_t)QKVN * DIM];      // fused wq|wk|wv fp16
__device__ __half g_wo2[(size_t)DIM * DIM];      // wo fp16

// ---------------- helpers ----------------
__device__ __forceinline__ uint32_t smem_u32(const void* p) {
    uint32_t a;
    asm("{ .reg .u64 t; cvta.to.shared.u64 t, %1; cvt.u32.u64 %0, t; }" : "=r"(a) : "l"(p));
    return a;
}

__device__ __forceinline__ void ldsm_x4(uint32_t* r, uint32_t addr) {
    asm volatile("ldmatrix.sync.aligned.m8n8.x4.shared.b16 {%0,%1,%2,%3}, [%4];"
        : "=r"(r[0]), "=r"(r[1]), "=r"(r[2]), "=r"(r[3]) : "r"(addr));
}
__device__ __forceinline__ void ldsm_x4_trans(uint32_t* r, uint32_t addr) {
    asm volatile("ldmatrix.sync.aligned.m8n8.x4.trans.shared.b16 {%0,%1,%2,%3}, [%4];"
        : "=r"(r[0]), "=r"(r[1]), "=r"(r[2]), "=r"(r[3]) : "r"(addr));
}

__device__ __forceinline__ void mma16816(float* d, const uint32_t* a, const uint32_t* b) {
    asm volatile("mma.sync.aligned.m16n8k16.row.col.f32.f16.f16.f32 "
        "{%0,%1,%2,%3}, {%4,%5,%6,%7}, {%8,%9}, {%0,%1,%2,%3};"
        : "+f"(d[0]), "+f"(d[1]), "+f"(d[2]), "+f"(d[3])
        : "r"(a[0]), "r"(a[1]), "r"(a[2]), "r"(a[3]), "r"(b[0]), "r"(b[1]));
}

__device__ __forceinline__ uint32_t packh2(float lo, float hi) {
    __half2 h = __floats2half2_rn(lo, hi);
    return *(uint32_t*)&h;
}

// =====================================================================
// fused convert: all fp32 weights/activations -> fp16, 2 float4/thread
// =====================================================================
#define CVT_TOTAL4 6815744
#define CVT_THREADS (CVT_TOTAL4 / 2)

__global__ void convert_all(const float* __restrict__ wq, const float* __restrict__ wk,
                            const float* __restrict__ wv, const float* __restrict__ wo,
                            const float* __restrict__ x,
                            __half* __restrict__ wf, __half* __restrict__ wo2,
                            __half* __restrict__ xh) {
    int t = blockIdx.x * 256 + threadIdx.x;
    if (t >= CVT_THREADS) return;
#pragma unroll
    for (int u = 0; u < 2; u++) {
        int i = t * 2 + u;
        const float* src;
        __half* dst;
        int off;
        if (i < 1048576)       { src = wq; dst = wf;                             off = i; }
        else if (i < 1310720)  { src = wk; dst = wf + (size_t)DIM * DIM;         off = i - 1048576; }
        else if (i < 1572864)  { src = wv; dst = wf + (size_t)(DIM + KVD) * DIM; off = i - 1310720; }
        else if (i < 2621440)  { src = wo; dst = wo2;                            off = i - 1572864; }
        else                   { src = x;  dst = xh;                             off = i - 2621440; }
        float4 v = ((const float4*)src)[off];
        __half2* op = (__half2*)dst;
        op[off * 2 + 0] = __floats2half2_rn(v.x, v.y);
        op[off * 2 + 1] = __floats2half2_rn(v.z, v.w);
    }
}

// =====================================================================
// GEMM via mma.sync fp16: C[M,N] = A @ B^T, fp32 accum.   (R14-best)
// CTA tile 128x128, BK=64, 128 threads (4 warps, warp tile 64x64),
// double-buffered cp.async. smem row stride 144B (ldmatrix conflict-free).
// 3 CTAs/SM (launch_bounds cap 168 regs).
// =====================================================================
#define TILE_B   18432          // 128 rows * 144 B
#define STAGE_B  (2 * TILE_B)   // 36864
#define GEMM_SMEM_BYTES (2 * STAGE_B)  // 73728

__device__ __forceinline__ void gemm_load_chunk(
    const __half* __restrict__ A, const __half* __restrict__ B,
    int bm, int bn, int K, int kc, uint32_t stbase, int tid) {
#pragma unroll
    for (int t = 0; t < 16; t++) {
        const int tile = t >> 3;                  // 0:A 1:B (compile-time)
        const int rem  = tid + (t & 7) * 128;     // 0..1023
        const int row  = rem >> 3;
        const int seg  = rem & 7;
        const __half* base = (tile == 0) ? A : B;
        const int grow = ((tile == 0) ? bm : bn) + row;
        const void* g = base + (size_t)grow * K + kc * 64 + seg * 8;
        uint32_t dst = stbase + (uint32_t)tile * TILE_B + (uint32_t)(row * 144 + seg * 16);
        asm volatile("cp.async.cg.shared.global [%0], [%1], 16;" :: "r"(dst), "l"(g) : "memory");
    }
    asm volatile("cp.async.commit_group;" ::: "memory");
}

template <bool ROPE_F16>
__global__ __launch_bounds__(128, 3)
void gemm_f16(const __half* __restrict__ A, const __half* __restrict__ B,
              void* __restrict__ Cout, int N, int K,
              const float* __restrict__ cosT, const float* __restrict__ sinT) {
    extern __shared__ char smem_raw[];
    const uint32_t sbase = smem_u32(smem_raw);

    const int tid  = threadIdx.x;
    const int wid  = tid >> 5;
    const int lane = tid & 31;
    const int warp_m = wid & 1;        // 2 warps along M (64 rows each)
    const int warp_n = wid >> 1;       // 2 warps along N (64 cols each)
    const int bm = blockIdx.y * 128;
    const int bn = blockIdx.x * 128;

    float acc[4][8][4];
#pragma unroll
    for (int i = 0; i < 4; i++)
#pragma unroll
        for (int j = 0; j < 8; j++)
#pragma unroll
            for (int v = 0; v < 4; v++) acc[i][j][v] = 0.0f;

    const uint32_t a_row = (uint32_t)(warp_m * 64 + (lane & 15));
    const uint32_t a_off = a_row * 144u + (uint32_t)((lane >> 4) * 16);
    const uint32_t b_row = (uint32_t)(warp_n * 64 + (lane & 7) + ((lane >> 4) & 1) * 8);
    const uint32_t b_off = b_row * 144u + (uint32_t)(((lane >> 3) & 1) * 16);

    const int NCHUNK = K >> 6;   // BK = 64

    gemm_load_chunk(A, B, bm, bn, K, 0, sbase, tid);

    for (int c = 0; c < NCHUNK; c++) {
        asm volatile("cp.async.wait_group 0;" ::: "memory");
        __syncthreads();
        if (c + 1 < NCHUNK)
            gemm_load_chunk(A, B, bm, bn, K, c + 1,
                            sbase + (uint32_t)((c + 1) & 1) * STAGE_B, tid);

        const uint32_t stage = (uint32_t)(c & 1) * STAGE_B;
#pragma unroll
        for (int ks = 0; ks < 4; ks++) {
            const uint32_t aa = sbase + stage + a_off + (uint32_t)ks * 32u;
            const uint32_t bb = sbase + stage + TILE_B + b_off + (uint32_t)ks * 32u;
            uint32_t af[4][4];
#pragma unroll
            for (int mt = 0; mt < 4; mt++)
                ldsm_x4(af[mt], aa + (uint32_t)mt * (16u * 144u));
#pragma unroll
            for (int nbh = 0; nbh < 2; nbh++) {
                uint32_t bf0[4], bf1[4];
                ldsm_x4(bf0, bb + (uint32_t)(nbh * 2 + 0) * (16u * 144u));
                ldsm_x4(bf1, bb + (uint32_t)(nbh * 2 + 1) * (16u * 144u));
#pragma unroll
                for (int mt = 0; mt < 4; mt++) {
                    mma16816(acc[mt][nbh * 4 + 0], af[mt], &bf0[0]);
                    mma16816(acc[mt][nbh * 4 + 1], af[mt], &bf0[2]);
                    mma16816(acc[mt][nbh * 4 + 2], af[mt], &bf1[0]);
                    mma16816(acc[mt][nbh * 4 + 3], af[mt], &bf1[2]);
                }
            }
        }
    }

    const int crow = lane >> 2;
    const int ccol = (lane & 3) * 2;
    const float qscale = 0.08838834764831845f;  // 1/sqrt(128)
#pragma unroll
    for (int mt = 0; mt < 4; mt++) {
#pragma unroll
        for (int nt = 0; nt < 8; nt++) {
            const int row = bm + warp_m * 64 + mt * 16 + crow;
            const int col = bn + warp_n * 64 + nt * 8 + ccol;
            if (ROPE_F16) {
                float2 v0 = make_float2(acc[mt][nt][0], acc[mt][nt][1]);
                float2 v1 = make_float2(acc[mt][nt][2], acc[mt][nt][3]);
                if (col < QKEND) {
                    const int j  = (col & (HD - 1)) >> 1;
                    const int s0 = row & (S_LEN - 1);
                    const int s1 = (row + 8) & (S_LEN - 1);
                    float c0 = cosT[s0 * 64 + j], n0 = sinT[s0 * 64 + j];
                    float c1 = cosT[s1 * 64 + j], n1 = sinT[s1 * 64 + j];
                    v0 = make_float2(v0.x * c0 - v0.y * n0, v0.x * n0 + v0.y * c0);
                    v1 = make_float2(v1.x * c1 - v1.y * n1, v1.x * n1 + v1.y * c1);
                }
                if (col < DIM) {   // Q region: fold attention scale
                    v0.x *= qscale; v0.y *= qscale;
                    v1.x *= qscale; v1.y *= qscale;
                }
                __half* Ch = (__half*)Cout;
                *(uint32_t*)&Ch[(size_t)row * N + col]       = packh2(v0.x, v0.y);
                *(uint32_t*)&Ch[(size_t)(row + 8) * N + col] = packh2(v1.x, v1.y);
            } else {
                float* Cf = (float*)Cout;
                *(float2*)&Cf[(size_t)row * N + col]       = make_float2(acc[mt][nt][0], acc[mt][nt][1]);
                *(float2*)&Cf[(size_t)(row + 8) * N + col] = make_float2(acc[mt][nt][2], acc[mt][nt][3]);
            }
        }
    }
}

// =====================================================================
// Tensor-core flash attention (causal, GQA).
// BM=128, BN=64, D=128, 256 threads (8 warps, each owns 16 q-rows).
// Q pre-scaled by 1/sqrt(128) in the QKV epilogue.
// Longest-first CTA ordering: qt = 7 - blockIdx.x.
// =====================================================================
#define FLA_KV_B    (64 * 136 * 2)                 // 17408 B
#define FLA_Q_B     (128 * 136 * 2)                // 34816 B
#define FLASH_SMEM_BYTES (FLA_Q_B + 4 * FLA_KV_B)  // 104448

__device__ __forceinline__ void fla_load_kv(const __half* src, uint32_t dst, int tid) {
#pragma unroll
    for (int i = 0; i < 4; i++) {
        int s = tid + i * 256;
        int row = s >> 4, seg = s & 15;
        const void* g = src + (size_t)row * QKVN + seg * 8;
        asm volatile("cp.async.cg.shared.global [%0], [%1], 16;"
            :: "r"(dst + (uint32_t)(row * 272 + seg * 16)), "l"(g) : "memory");
    }
}

__global__ __launch_bounds__(256)
void flash_mma(const __half* __restrict__ QKVh, __half* __restrict__ Oh) {
    const int qt = (int)(gridDim.x - 1 - blockIdx.x);   // longest-first
    const int h  = blockIdx.y;
    const int b  = blockIdx.z;
    const int g  = h >> 2;

    extern __shared__ char smraw[];
    const uint32_t sQ = smem_u32(smraw);
    const uint32_t sK = sQ + FLA_Q_B;
    const uint32_t sV = sK + 2 * FLA_KV_B;

    const int tid  = threadIdx.x;
    const int wid  = tid >> 5;
    const int lane = tid & 31;

    {
        const __half* qsrc = QKVh + (size_t)(b * S_LEN + qt * 128) * QKVN + h * HD;
#pragma unroll
        for (int i = 0; i < 8; i++) {
            int s = tid + i * 256;
            int row = s >> 4, seg = s & 15;
            const void* gp = qsrc + (size_t)row * QKVN + seg * 8;
            asm volatile("cp.async.cg.shared.global [%0], [%1], 16;"
                :: "r"(sQ + (uint32_t)(row * 272 + seg * 16)), "l"(gp) : "memory");
        }
        const __half* ksrc = QKVh + (size_t)(b * S_LEN) * QKVN + DIM + g * HD;
        fla_load_kv(ksrc, sK, tid);
        fla_load_kv(ksrc + KVD, sV, tid);
        asm volatile("cp.async.commit_group;" ::: "memory");
    }

    const uint32_t a_base = sQ + (uint32_t)((wid * 16 + (lane & 15)) * 272 + (lane >> 4) * 16);
    const uint32_t kb_off = (uint32_t)(((lane & 7) + ((lane >> 4) & 1) * 8) * 272 + ((lane >> 3) & 1) * 16);
    const uint32_t vb_off = (uint32_t)(((lane & 7) + ((lane >> 3) & 1) * 8) * 272 + ((lane >> 4) & 1) * 16);

    float o[16][4];
#pragma unroll
    for (int j = 0; j < 16; j++)
#pragma unroll
        for (int v = 0; v < 4; v++) o[j][v] = 0.0f;
    float m0 = -INFINITY, m1 = -INFINITY, l0 = 0.0f, l1 = 0.0f;

    asm volatile("cp.async.wait_group 0;" ::: "memory");
    __syncthreads();

    uint32_t qa[8][4];
#pragma unroll
    for (int ks = 0; ks < 8; ks++) ldsm_x4(qa[ks], a_base + (uint32_t)ks * 32u);

    const int rb0 = wid * 16 + (lane >> 2);
    const int rb1 = rb0 + 8;
    const int cb  = (lane & 3) * 2;
    const int qrow0 = qt * 128 + rb0;
    const int qrow1 = qrow0 + 8;
    const int warp_row_max = qt * 128 + wid * 16 + 15;

    const int njt = 2 * qt + 2;
    for (int jt = 0; jt < njt; jt++) {
        const uint32_t buf = (uint32_t)(jt & 1) * FLA_KV_B;
        if (jt > 0) {
            asm volatile("cp.async.wait_group 0;" ::: "memory");
            __syncthreads();
        }
        if (jt + 1 < njt) {
            const __half* ksrc = QKVh + (size_t)(b * S_LEN + (jt + 1) * 64) * QKVN + DIM + g * HD;
            const uint32_t nbuf = (uint32_t)((jt + 1) & 1) * FLA_KV_B;
            fla_load_kv(ksrc, sK + nbuf, tid);
            fla_load_kv(ksrc + KVD, sV + nbuf, tid);
            asm volatile("cp.async.commit_group;" ::: "memory");
        }

        if (jt * 64 > warp_row_max) continue;

        // ---- S = Q K^T (Q pre-scaled) ----
        float s[8][4];
#pragma unroll
        for (int j = 0; j < 8; j++)
#pragma unroll
            for (int v = 0; v < 4; v++) s[j][v] = 0.0f;

#pragma unroll
        for (int ks = 0; ks < 8; ks++) {
            const uint32_t bb = sK + buf + kb_off + (uint32_t)ks * 32u;
#pragma unroll
            for (int nb = 0; nb < 4; nb++) {
                uint32_t bf[4];
                ldsm_x4(bf, bb + (uint32_t)nb * (16u * 272u));
                mma16816(s[nb * 2 + 0], qa[ks], &bf[0]);
                mma16816(s[nb * 2 + 1], qa[ks], &bf[2]);
            }
        }

        if (jt >= 2 * qt) {
#pragma unroll
            for (int j = 0; j < 8; j++) {
                const int c0 = jt * 64 + j * 8 + cb;
                if (c0 > qrow0)     s[j][0] = -1e30f;
                if (c0 + 1 > qrow0) s[j][1] = -1e30f;
                if (c0 > qrow1)     s[j][2] = -1e30f;
                if (c0 + 1 > qrow1) s[j][3] = -1e30f;
            }
        }

        // ---- online softmax ----
        float mx0 = -INFINITY, mx1 = -INFINITY;
#pragma unroll
        for (int j = 0; j < 8; j++) {
            mx0 = fmaxf(mx0, fmaxf(s[j][0], s[j][1]));
            mx1 = fmaxf(mx1, fmaxf(s[j][2], s[j][3]));
        }
        mx0 = fmaxf(mx0, __shfl_xor_sync(0xffffffffu, mx0, 1));
        mx0 = fmaxf(mx0, __shfl_xor_sync(0xffffffffu, mx0, 2));
        mx1 = fmaxf(mx1, __shfl_xor_sync(0xffffffffu, mx1, 1));
        mx1 = fmaxf(mx1, __shfl_xor_sync(0xffffffffu, mx1, 2));
        const float mn0 = fmaxf(m0, mx0);
        const float mn1 = fmaxf(m1, mx1);
        const float al0 = __expf(m0 - mn0);
        const float al1 = __expf(m1 - mn1);
        m0 = mn0; m1 = mn1;

        float sum0 = 0.0f, sum1 = 0.0f;
#pragma unroll
        for (int j = 0; j < 8; j++) {
            s[j][0] = __expf(s[j][0] - mn0);
            s[j][1] = __expf(s[j][1] - mn0);
            s[j][2] = __expf(s[j][2] - mn1);
            s[j][3] = __expf(s[j][3] - mn1);
            sum0 += s[j][0] + s[j][1];
            sum1 += s[j][2] + s[j][3];
        }
        sum0 += __shfl_xor_sync(0xffffffffu, sum0, 1);
        sum0 += __shfl_xor_sync(0xffffffffu, sum0, 2);
        sum1 += __shfl_xor_sync(0xffffffffu, sum1, 1);
        sum1 += __shfl_xor_sync(0xffffffffu, sum1, 2);
        l0 = l0 * al0 + sum0;
        l1 = l1 * al1 + sum1;

#pragma unroll
        for (int j = 0; j < 16; j++) {
            o[j][0] *= al0; o[j][1] *= al0; o[j][2] *= al1; o[j][3] *= al1;
        }

        // ---- O += P V ----
#pragma unroll
        for (int ksp = 0; ksp < 4; ksp++) {
            uint32_t pa[4];
            pa[0] = packh2(s[2 * ksp][0],     s[2 * ksp][1]);
            pa[1] = packh2(s[2 * ksp][2],     s[2 * ksp][3]);
            pa[2] = packh2(s[2 * ksp + 1][0], s[2 * ksp + 1][1]);
            pa[3] = packh2(s[2 * ksp + 1][2], s[2 * ksp + 1][3]);
            const uint32_t vb = sV + buf + vb_off + (uint32_t)ksp * (16u * 272u);
#pragma unroll
            for (int nb = 0; nb < 8; nb++) {
                uint32_t bf[4];
                ldsm_x4_trans(bf, vb + (uint32_t)nb * 32u);
                mma16816(o[nb * 2 + 0], pa, &bf[0]);
                mma16816(o[nb * 2 + 1], pa, &bf[2]);
            }
        }
    }

    const float inv0 = 1.0f / l0;
    const float inv1 = 1.0f / l1;
    const size_t row0 = (size_t)(b * S_LEN + qt * 128 + rb0);
    const size_t row1 = row0 + 8;
#pragma unroll
    for (int j = 0; j < 16; j++) {
        const int col = h * HD + j * 8 + cb;
        uint32_t p0 = packh2(o[j][0] * inv0, o[j][1] * inv0);
        uint32_t p1 = packh2(o[j][2] * inv1, o[j][3] * inv1);
        *(uint32_t*)&Oh[row0 * DIM + col] = p0;
        *(uint32_t*)&Oh[row1 * DIM + col] = p1;
    }
}

// =====================================================================
// launch
// =====================================================================
extern "C" void kernel_launch(void* const* d_in, const int* in_sizes, int n_in,
                              void* d_out, int out_size) {
    (void)in_sizes; (void)n_in; (void)out_size;
    const float* x    = (const float*)d_in[0];
    const float* cosT = (const float*)d_in[1];
    const float* sinT = (const float*)d_in[2];
    const float* wq   = (const float*)d_in[3];
    const float* wk   = (const float*)d_in[4];
    const float* wv   = (const float*)d_in[5];
    const float* wo   = (const float*)d_in[6];
    float* out = (float*)d_out;

    __half *pqkvh, *xh, *oh, *wf, *wo2;
    cudaGetSymbolAddress((void**)&pqkvh, g_qkvh);
    cudaGetSymbolAddress((void**)&xh, g_xh);
    cudaGetSymbolAddress((void**)&oh, g_oh);
    cudaGetSymbolAddress((void**)&wf, g_wf);
    cudaGetSymbolAddress((void**)&wo2, g_wo2);

    cudaFuncSetAttribute(flash_mma, cudaFuncAttributeMaxDynamicSharedMemorySize, FLASH_SMEM_BYTES);
    cudaFuncSetAttribute(gemm_f16<true>,  cudaFuncAttributeMaxDynamicSharedMemorySize, GEMM_SMEM_BYTES);
    cudaFuncSetAttribute(gemm_f16<false>, cudaFuncAttributeMaxDynamicSharedMemorySize, GEMM_SMEM_BYTES);

    // one fused convert launch (2 float4 per thread)
    convert_all<<<(CVT_THREADS + 255) / 256, 256>>>(wq, wk, wv, wo, x, wf, wo2, xh);

    // fused QKV projection with RoPE + Q-scale epilogue, fp16 out
    gemm_f16<true><<<dim3(QKVN / 128, MTOT / 128), 128, GEMM_SMEM_BYTES>>>(
        xh, wf, pqkvh, QKVN, DIM, cosT, sinT);

    // tensor-core flash attention (writes fp16 O directly, longest-first)
    flash_mma<<<dim3(S_LEN / 128, NH, B_SZ), 256, FLASH_SMEM_BYTES>>>(pqkvh, oh);

    // output projection (fp32 out)
    gemm_f16<false><<<dim3(DIM / 128, MTOT / 128), 128, GEMM_SMEM_BYTES>>>(
        oh, wo2, out, DIM, DIM, nullptr, nullptr);
}

// round 17
// speedup vs baseline: 1.0206x; 1.0030x over previous
#include <cuda_runtime.h>
#include <cuda_fp16.h>
#include <math.h>
#include <stdint.h>

#define B_SZ  8
#define S_LEN 1024
#define NH    16
#define NKV   4
#define HD    128
#define DIM   2048
#define MTOT  (B_SZ * S_LEN)   // 8192
#define KVD   (NKV * HD)       // 512
#define QKVN  (DIM + 2 * KVD)  // 3072
#define QKEND (DIM + KVD)      // 2560: cols < this get RoPE

// ---------------- static scratch (allocation-free) ----------------
__device__ __half g_qkvh[(size_t)MTOT * QKVN];   // fused Q|K|V fp16 (rope applied, Q pre-scaled)
__device__ __half g_xh[(size_t)MTOT * DIM];      // x fp16
__device__ __half g_oh[(size_t)MTOT * DIM];      // attn out fp16
__device__ __half g_wf[(size_t)QKVN * DIM];      // fused wq|wk|wv fp16
__device__ __half g_wo2[(size_t)DIM * DIM];      // wo fp16

// ---------------- helpers ----------------
__device__ __forceinline__ uint32_t smem_u32(const void* p) {
    uint32_t a;
    asm("{ .reg .u64 t; cvta.to.shared.u64 t, %1; cvt.u32.u64 %0, t; }" : "=r"(a) : "l"(p));
    return a;
}

__device__ __forceinline__ void ldsm_x4(uint32_t* r, uint32_t addr) {
    asm volatile("ldmatrix.sync.aligned.m8n8.x4.shared.b16 {%0,%1,%2,%3}, [%4];"
        : "=r"(r[0]), "=r"(r[1]), "=r"(r[2]), "=r"(r[3]) : "r"(addr));
}
__device__ __forceinline__ void ldsm_x4_trans(uint32_t* r, uint32_t addr) {
    asm volatile("ldmatrix.sync.aligned.m8n8.x4.trans.shared.b16 {%0,%1,%2,%3}, [%4];"
        : "=r"(r[0]), "=r"(r[1]), "=r"(r[2]), "=r"(r[3]) : "r"(addr));
}

__device__ __forceinline__ void mma16816(float* d, const uint32_t* a, const uint32_t* b) {
    asm volatile("mma.sync.aligned.m16n8k16.row.col.f32.f16.f16.f32 "
        "{%0,%1,%2,%3}, {%4,%5,%6,%7}, {%8,%9}, {%0,%1,%2,%3};"
        : "+f"(d[0]), "+f"(d[1]), "+f"(d[2]), "+f"(d[3])
        : "r"(a[0]), "r"(a[1]), "r"(a[2]), "r"(a[3]), "r"(b[0]), "r"(b[1]));
}

__device__ __forceinline__ uint32_t packh2(float lo, float hi) {
    __half2 h = __floats2half2_rn(lo, hi);
    return *(uint32_t*)&h;
}

// =====================================================================
// fused convert: all fp32 weights/activations -> fp16, 2 float4/thread
// =====================================================================
#define CVT_TOTAL4 6815744
#define CVT_THREADS (CVT_TOTAL4 / 2)

__global__ void convert_all(const float* __restrict__ wq, const float* __restrict__ wk,
                            const float* __restrict__ wv, const float* __restrict__ wo,
                            const float* __restrict__ x,
                            __half* __restrict__ wf, __half* __restrict__ wo2,
                            __half* __restrict__ xh) {
    int t = blockIdx.x * 256 + threadIdx.x;
    if (t >= CVT_THREADS) return;
#pragma unroll
    for (int u = 0; u < 2; u++) {
        int i = t * 2 + u;
        const float* src;
        __half* dst;
        int off;
        if (i < 1048576)       { src = wq; dst = wf;                             off = i; }
        else if (i < 1310720)  { src = wk; dst = wf + (size_t)DIM * DIM;         off = i - 1048576; }
        else if (i < 1572864)  { src = wv; dst = wf + (size_t)(DIM + KVD) * DIM; off = i - 1310720; }
        else if (i < 2621440)  { src = wo; dst = wo2;                            off = i - 1572864; }
        else                   { src = x;  dst = xh;                             off = i - 2621440; }
        float4 v = ((const float4*)src)[off];
        __half2* op = (__half2*)dst;
        op[off * 2 + 0] = __floats2half2_rn(v.x, v.y);
        op[off * 2 + 1] = __floats2half2_rn(v.z, v.w);
    }
}

// =====================================================================
// GEMM via mma.sync fp16: C[M,N] = A @ B^T, fp32 accum.   (R14-best)
// CTA tile 128x128, BK=64, 128 threads (4 warps, warp tile 64x64),
// double-buffered cp.async. smem row stride 144B (ldmatrix conflict-free).
// 3 CTAs/SM (launch_bounds cap 168 regs).
// =====================================================================
#define TILE_B   18432          // 128 rows * 144 B
#define STAGE_B  (2 * TILE_B)   // 36864
#define GEMM_SMEM_BYTES (2 * STAGE_B)  // 73728

__device__ __forceinline__ void gemm_load_chunk(
    const __half* __restrict__ A, const __half* __restrict__ B,
    int bm, int bn, int K, int kc, uint32_t stbase, int tid) {
#pragma unroll
    for (int t = 0; t < 16; t++) {
        const int tile = t >> 3;                  // 0:A 1:B (compile-time)
        const int rem  = tid + (t & 7) * 128;     // 0..1023
        const int row  = rem >> 3;
        const int seg  = rem & 7;
        const __half* base = (tile == 0) ? A : B;
        const int grow = ((tile == 0) ? bm : bn) + row;
        const void* g = base + (size_t)grow * K + kc * 64 + seg * 8;
        uint32_t dst = stbase + (uint32_t)tile * TILE_B + (uint32_t)(row * 144 + seg * 16);
        asm volatile("cp.async.cg.shared.global [%0], [%1], 16;" :: "r"(dst), "l"(g) : "memory");
    }
    asm volatile("cp.async.commit_group;" ::: "memory");
}

template <bool ROPE_F16>
__global__ __launch_bounds__(128, 3)
void gemm_f16(const __half* __restrict__ A, const __half* __restrict__ B,
              void* __restrict__ Cout, int N, int K,
              const float* __restrict__ cosT, const float* __restrict__ sinT) {
    extern __shared__ char smem_raw[];
    const uint32_t sbase = smem_u32(smem_raw);

    const int tid  = threadIdx.x;
    const int wid  = tid >> 5;
    const int lane = tid & 31;
    const int warp_m = wid & 1;        // 2 warps along M (64 rows each)
    const int warp_n = wid >> 1;       // 2 warps along N (64 cols each)
    const int bm = blockIdx.y * 128;
    const int bn = blockIdx.x * 128;

    float acc[4][8][4];
#pragma unroll
    for (int i = 0; i < 4; i++)
#pragma unroll
        for (int j = 0; j < 8; j++)
#pragma unroll
            for (int v = 0; v < 4; v++) acc[i][j][v] = 0.0f;

    const uint32_t a_row = (uint32_t)(warp_m * 64 + (lane & 15));
    const uint32_t a_off = a_row * 144u + (uint32_t)((lane >> 4) * 16);
    const uint32_t b_row = (uint32_t)(warp_n * 64 + (lane & 7) + ((lane >> 4) & 1) * 8);
    const uint32_t b_off = b_row * 144u + (uint32_t)(((lane >> 3) & 1) * 16);

    const int NCHUNK = K >> 6;   // BK = 64

    gemm_load_chunk(A, B, bm, bn, K, 0, sbase, tid);

    for (int c = 0; c < NCHUNK; c++) {
        asm volatile("cp.async.wait_group 0;" ::: "memory");
        __syncthreads();
        if (c + 1 < NCHUNK)
            gemm_load_chunk(A, B, bm, bn, K, c + 1,
                            sbase + (uint32_t)((c + 1) & 1) * STAGE_B, tid);

        const uint32_t stage = (uint32_t)(c & 1) * STAGE_B;
#pragma unroll
        for (int ks = 0; ks < 4; ks++) {
            const uint32_t aa = sbase + stage + a_off + (uint32_t)ks * 32u;
            const uint32_t bb = sbase + stage + TILE_B + b_off + (uint32_t)ks * 32u;
            uint32_t af[4][4];
#pragma unroll
            for (int mt = 0; mt < 4; mt++)
                ldsm_x4(af[mt], aa + (uint32_t)mt * (16u * 144u));
#pragma unroll
            for (int nbh = 0; nbh < 2; nbh++) {
                uint32_t bf0[4], bf1[4];
                ldsm_x4(bf0, bb + (uint32_t)(nbh * 2 + 0) * (16u * 144u));
                ldsm_x4(bf1, bb + (uint32_t)(nbh * 2 + 1) * (16u * 144u));
#pragma unroll
                for (int mt = 0; mt < 4; mt++) {
                    mma16816(acc[mt][nbh * 4 + 0], af[mt], &bf0[0]);
                    mma16816(acc[mt][nbh * 4 + 1], af[mt], &bf0[2]);
                    mma16816(acc[mt][nbh * 4 + 2], af[mt], &bf1[0]);
                    mma16816(acc[mt][nbh * 4 + 3], af[mt], &bf1[2]);
                }
            }
        }
    }

    const int crow = lane >> 2;
    const int ccol = (lane & 3) * 2;
    const float qscale = 0.08838834764831845f;  // 1/sqrt(128)
#pragma unroll
    for (int mt = 0; mt < 4; mt++) {
#pragma unroll
        for (int nt = 0; nt < 8; nt++) {
            const int row = bm + warp_m * 64 + mt * 16 + crow;
            const int col = bn + warp_n * 64 + nt * 8 + ccol;
            if (ROPE_F16) {
                float2 v0 = make_float2(acc[mt][nt][0], acc[mt][nt][1]);
                float2 v1 = make_float2(acc[mt][nt][2], acc[mt][nt][3]);
                if (col < QKEND) {
                    const int j  = (col & (HD - 1)) >> 1;
                    const int s0 = row & (S_LEN - 1);
                    const int s1 = (row + 8) & (S_LEN - 1);
                    float c0 = cosT[s0 * 64 + j], n0 = sinT[s0 * 64 + j];
                    float c1 = cosT[s1 * 64 + j], n1 = sinT[s1 * 64 + j];
                    v0 = make_float2(v0.x * c0 - v0.y * n0, v0.x * n0 + v0.y * c0);
                    v1 = make_float2(v1.x * c1 - v1.y * n1, v1.x * n1 + v1.y * c1);
                }
                if (col < DIM) {   // Q region: fold attention scale
                    v0.x *= qscale; v0.y *= qscale;
                    v1.x *= qscale; v1.y *= qscale;
                }
                __half* Ch = (__half*)Cout;
                *(uint32_t*)&Ch[(size_t)row * N + col]       = packh2(v0.x, v0.y);
                *(uint32_t*)&Ch[(size_t)(row + 8) * N + col] = packh2(v1.x, v1.y);
            } else {
                float* Cf = (float*)Cout;
                *(float2*)&Cf[(size_t)row * N + col]       = make_float2(acc[mt][nt][0], acc[mt][nt][1]);
                *(float2*)&Cf[(size_t)(row + 8) * N + col] = make_float2(acc[mt][nt][2], acc[mt][nt][3]);
            }
        }
    }
}

// =====================================================================
// Tensor-core flash attention (causal, GQA).
// BM=128, BN=64, D=128, 256 threads (8 warps, each owns 16 q-rows).
// Q pre-scaled by 1/sqrt(128) in the QKV epilogue.
// __launch_bounds__(256,2) forces <=128 regs -> 2 CTAs/SM.
// Q fragments re-loaded from smem each jt (saves 32 regs vs hoisting).
// =====================================================================
#define FLA_KV_B    (64 * 136 * 2)                 // 17408 B
#define FLA_Q_B     (128 * 136 * 2)                // 34816 B
#define FLASH_SMEM_BYTES (FLA_Q_B + 4 * FLA_KV_B)  // 104448

__device__ __forceinline__ void fla_load_kv(const __half* src, uint32_t dst, int tid) {
#pragma unroll
    for (int i = 0; i < 4; i++) {
        int s = tid + i * 256;
        int row = s >> 4, seg = s & 15;
        const void* g = src + (size_t)row * QKVN + seg * 8;
        asm volatile("cp.async.cg.shared.global [%0], [%1], 16;"
            :: "r"(dst + (uint32_t)(row * 272 + seg * 16)), "l"(g) : "memory");
    }
}

__global__ __launch_bounds__(256, 2)
void flash_mma(const __half* __restrict__ QKVh, __half* __restrict__ Oh) {
    const int qt = blockIdx.x;          // 0..7 (128-row q tiles)
    const int h  = blockIdx.y;
    const int b  = blockIdx.z;
    const int g  = h >> 2;

    extern __shared__ char smraw[];
    const uint32_t sQ = smem_u32(smraw);
    const uint32_t sK = sQ + FLA_Q_B;
    const uint32_t sV = sK + 2 * FLA_KV_B;

    const int tid  = threadIdx.x;
    const int wid  = tid >> 5;
    const int lane = tid & 31;

    {
        const __half* qsrc = QKVh + (size_t)(b * S_LEN + qt * 128) * QKVN + h * HD;
#pragma unroll
        for (int i = 0; i < 8; i++) {
            int s = tid + i * 256;
            int row = s >> 4, seg = s & 15;
            const void* gp = qsrc + (size_t)row * QKVN + seg * 8;
            asm volatile("cp.async.cg.shared.global [%0], [%1], 16;"
                :: "r"(sQ + (uint32_t)(row * 272 + seg * 16)), "l"(gp) : "memory");
        }
        const __half* ksrc = QKVh + (size_t)(b * S_LEN) * QKVN + DIM + g * HD;
        fla_load_kv(ksrc, sK, tid);
        fla_load_kv(ksrc + KVD, sV, tid);
        asm volatile("cp.async.commit_group;" ::: "memory");
    }

    const uint32_t a_base = sQ + (uint32_t)((wid * 16 + (lane & 15)) * 272 + (lane >> 4) * 16);
    const uint32_t kb_off = (uint32_t)(((lane & 7) + ((lane >> 4) & 1) * 8) * 272 + ((lane >> 3) & 1) * 16);
    const uint32_t vb_off = (uint32_t)(((lane & 7) + ((lane >> 3) & 1) * 8) * 272 + ((lane >> 4) & 1) * 16);

    float o[16][4];
#pragma unroll
    for (int j = 0; j < 16; j++)
#pragma unroll
        for (int v = 0; v < 4; v++) o[j][v] = 0.0f;
    float m0 = -INFINITY, m1 = -INFINITY, l0 = 0.0f, l1 = 0.0f;

    asm volatile("cp.async.wait_group 0;" ::: "memory");
    __syncthreads();

    const int rb0 = wid * 16 + (lane >> 2);
    const int rb1 = rb0 + 8;
    const int cb  = (lane & 3) * 2;
    const int qrow0 = qt * 128 + rb0;
    const int qrow1 = qrow0 + 8;
    const int warp_row_max = qt * 128 + wid * 16 + 15;

    const int njt = 2 * qt + 2;
    for (int jt = 0; jt < njt; jt++) {
        const uint32_t buf = (uint32_t)(jt & 1) * FLA_KV_B;
        if (jt > 0) {
            asm volatile("cp.async.wait_group 0;" ::: "memory");
            __syncthreads();
        }
        if (jt + 1 < njt) {
            const __half* ksrc = QKVh + (size_t)(b * S_LEN + (jt + 1) * 64) * QKVN + DIM + g * HD;
            const uint32_t nbuf = (uint32_t)((jt + 1) & 1) * FLA_KV_B;
            fla_load_kv(ksrc, sK + nbuf, tid);
            fla_load_kv(ksrc + KVD, sV + nbuf, tid);
            asm volatile("cp.async.commit_group;" ::: "memory");
        }

        if (jt * 64 > warp_row_max) continue;

        // ---- S = Q K^T (Q frags from smem each step; Q pre-scaled) ----
        float s[8][4];
#pragma unroll
        for (int j = 0; j < 8; j++)
#pragma unroll
            for (int v = 0; v < 4; v++) s[j][v] = 0.0f;

#pragma unroll
        for (int ks = 0; ks < 8; ks++) {
            uint32_t qa[4];
            ldsm_x4(qa, a_base + (uint32_t)ks * 32u);
            const uint32_t bb = sK + buf + kb_off + (uint32_t)ks * 32u;
#pragma unroll
            for (int nb = 0; nb < 4; nb++) {
                uint32_t bf[4];
                ldsm_x4(bf, bb + (uint32_t)nb * (16u * 272u));
                mma16816(s[nb * 2 + 0], qa, &bf[0]);
                mma16816(s[nb * 2 + 1], qa, &bf[2]);
            }
        }

        if (jt >= 2 * qt) {
#pragma unroll
            for (int j = 0; j < 8; j++) {
                const int c0 = jt * 64 + j * 8 + cb;
                if (c0 > qrow0)     s[j][0] = -1e30f;
                if (c0 + 1 > qrow0) s[j][1] = -1e30f;
                if (c0 > qrow1)     s[j][2] = -1e30f;
                if (c0 + 1 > qrow1) s[j][3] = -1e30f;
            }
        }

        // ---- online softmax ----
        float mx0 = -INFINITY, mx1 = -INFINITY;
#pragma unroll
        for (int j = 0; j < 8; j++) {
            mx0 = fmaxf(mx0, fmaxf(s[j][0], s[j][1]));
            mx1 = fmaxf(mx1, fmaxf(s[j][2], s[j][3]));
        }
        mx0 = fmaxf(mx0, __shfl_xor_sync(0xffffffffu, mx0, 1));
        mx0 = fmaxf(mx0, __shfl_xor_sync(0xffffffffu, mx0, 2));
        mx1 = fmaxf(mx1, __shfl_xor_sync(0xffffffffu, mx1, 1));
        mx1 = fmaxf(mx1, __shfl_xor_sync(0xffffffffu, mx1, 2));
        const float mn0 = fmaxf(m0, mx0);
        const float mn1 = fmaxf(m1, mx1);
        const float al0 = __expf(m0 - mn0);
        const float al1 = __expf(m1 - mn1);
        m0 = mn0; m1 = mn1;

        float sum0 = 0.0f, sum1 = 0.0f;
#pragma unroll
        for (int j = 0; j < 8; j++) {
            s[j][0] = __expf(s[j][0] - mn0);
            s[j][1] = __expf(s[j][1] - mn0);
            s[j][2] = __expf(s[j][2] - mn1);
            s[j][3] = __expf(s[j][3] - mn1);
            sum0 += s[j][0] + s[j][1];
            sum1 += s[j][2] + s[j][3];
        }
        sum0 += __shfl_xor_sync(0xffffffffu, sum0, 1);
        sum0 += __shfl_xor_sync(0xffffffffu, sum0, 2);
        sum1 += __shfl_xor_sync(0xffffffffu, sum1, 1);
        sum1 += __shfl_xor_sync(0xffffffffu, sum1, 2);
        l0 = l0 * al0 + sum0;
        l1 = l1 * al1 + sum1;

#pragma unroll
        for (int j = 0; j < 16; j++) {
            o[j][0] *= al0; o[j][1] *= al0; o[j][2] *= al1; o[j][3] *= al1;
        }

        // ---- O += P V ----
#pragma unroll
        for (int ksp = 0; ksp < 4; ksp++) {
            uint32_t pa[4];
            pa[0] = packh2(s[2 * ksp][0],     s[2 * ksp][1]);
            pa[1] = packh2(s[2 * ksp][2],     s[2 * ksp][3]);
            pa[2] = packh2(s[2 * ksp + 1][0], s[2 * ksp + 1][1]);
            pa[3] = packh2(s[2 * ksp + 1][2], s[2 * ksp + 1][3]);
            const uint32_t vb = sV + buf + vb_off + (uint32_t)ksp * (16u * 272u);
#pragma unroll
            for (int nb = 0; nb < 8; nb++) {
                uint32_t bf[4];
                ldsm_x4_trans(bf, vb + (uint32_t)nb * 32u);
                mma16816(o[nb * 2 + 0], pa, &bf[0]);
                mma16816(o[nb * 2 + 1], pa, &bf[2]);
            }
        }
    }

    const float inv0 = 1.0f / l0;
    const float inv1 = 1.0f / l1;
    const size_t row0 = (size_t)(b * S_LEN + qt * 128 + rb0);
    const size_t row1 = row0 + 8;
#pragma unroll
    for (int j = 0; j < 16; j++) {
        const int col = h * HD + j * 8 + cb;
        uint32_t p0 = packh2(o[j][0] * inv0, o[j][1] * inv0);
        uint32_t p1 = packh2(o[j][2] * inv1, o[j][3] * inv1);
        *(uint32_t*)&Oh[row0 * DIM + col] = p0;
        *(uint32_t*)&Oh[row1 * DIM + col] = p1;
    }
}

// =====================================================================
// launch
// =====================================================================
extern "C" void kernel_launch(void* const* d_in, const int* in_sizes, int n_in,
                              void* d_out, int out_size) {
    (void)in_sizes; (void)n_in; (void)out_size;
    const float* x    = (const float*)d_in[0];
    const float* cosT = (const float*)d_in[1];
    const float* sinT = (const float*)d_in[2];
    const float* wq   = (const float*)d_in[3];
    const float* wk   = (const float*)d_in[4];
    const float* wv   = (const float*)d_in[5];
    const float* wo   = (const float*)d_in[6];
    float* out = (float*)d_out;

    __half *pqkvh, *xh, *oh, *wf, *wo2;
    cudaGetSymbolAddress((void**)&pqkvh, g_qkvh);
    cudaGetSymbolAddress((void**)&xh, g_xh);
    cudaGetSymbolAddress((void**)&oh, g_oh);
    cudaGetSymbolAddress((void**)&wf, g_wf);
    cudaGetSymbolAddress((void**)&wo2, g_wo2);

    cudaFuncSetAttribute(flash_mma, cudaFuncAttributeMaxDynamicSharedMemorySize, FLASH_SMEM_BYTES);
    cudaFuncSetAttribute(gemm_f16<true>,  cudaFuncAttributeMaxDynamicSharedMemorySize, GEMM_SMEM_BYTES);
    cudaFuncSetAttribute(gemm_f16<false>, cudaFuncAttributeMaxDynamicSharedMemorySize, GEMM_SMEM_BYTES);

    // one fused convert launch (2 float4 per thread)
    convert_all<<<(CVT_THREADS + 255) / 256, 256>>>(wq, wk, wv, wo, x, wf, wo2, xh);

    // fused QKV projection with RoPE + Q-scale epilogue, fp16 out
    gemm_f16<true><<<dim3(QKVN / 128, MTOT / 128), 128, GEMM_SMEM_BYTES>>>(
        xh, wf, pqkvh, QKVN, DIM, cosT, sinT);

    // tensor-core flash attention (writes fp16 O directly)
    flash_mma<<<dim3(S_LEN / 128, NH, B_SZ), 256, FLASH_SMEM_BYTES>>>(pqkvh, oh);

    // output projection (fp32 out)
    gemm_f16<false><<<dim3(DIM / 128, MTOT / 128), 128, GEMM_SMEM_BYTES>>>(
        oh, wo2, out, DIM, DIM, nullptr, nullptr);
}